// round 10
// baseline (speedup 1.0000x reference)
#include <cuda_runtime.h>
#include <cuda_bf16.h>
#include <cstdint>

#define NPOS 9
#define NROWS 16384              // T*B
#define D 128
#define GRID_CTAS 128            // 128 rows per CTA, contiguous; 1 wave (<=148 SMs)
#define NTHREADS 256
#define BFRAG_PER_CTA 288        // 36864 / 128 exactly
#define NBFRAG (NPOS * 128 * 32) // 36864 uint4 entries

__device__ uint4 g_bfrag[NBFRAG];   // {BH0,BH1,BL0,BL1} per (p, q*16+nb, lane)
__device__ int g_arrive;            // zero at entry; last CTA resets
__device__ int g_exit;

// smem: A fragments (hi 32KB, lo 32KB) + control (aux needs 1924B -> 2048)
#define OFF_AHI 0
#define OFF_ALO 32768
#define OFF_AUX 65536
#define SMEM_BYTES (65536 + 2048)

__device__ __forceinline__ void split2(float x, float y, uint32_t& hi, uint32_t& lo) {
    __nv_bfloat162 h = __floats2bfloat162_rn(x, y);
    float hx = __bfloat162float(h.x), hy = __bfloat162float(h.y);
    __nv_bfloat162 l = __floats2bfloat162_rn(x - hx, y - hy);
    hi = *(uint32_t*)&h;
    lo = *(uint32_t*)&l;
}

#define MMA16816(c0, c1, c2, c3, a0, a1, a2, a3, b0, b1)                      \
    asm volatile(                                                             \
        "mma.sync.aligned.m16n8k16.row.col.f32.bf16.bf16.f32 "                \
        "{%0,%1,%2,%3}, {%4,%5,%6,%7}, {%8,%9}, {%0,%1,%2,%3};"               \
        : "+f"(c0), "+f"(c1), "+f"(c2), "+f"(c3)                              \
        : "r"(a0), "r"(a1), "r"(a2), "r"(a3), "r"(b0), "r"(b1))

__global__ void __launch_bounds__(NTHREADS, 1)
fused_transfer(const void* __restrict__ pos_raw,
               const float* __restrict__ x,
               const float* __restrict__ table,
               float* __restrict__ out)
{
    extern __shared__ char base[];
    int*  scnt   = (int*)(base + OFF_AUX);   // [16] group counters
    int*  seg    = scnt + 16;                // [16] segment starts
    int*  perm   = seg + 16;                 // [128] sorted-slot -> local row
    int*  parr   = perm + 128;               // [128] local row -> group
    int*  rnk    = parr + 128;               // [128] local row -> rank in group
    int4* items  = (int4*)(rnk + 128);       // [16]  (block, p, s, e) ; 16B-aligned
    int*  nitems = (int*)(items + 16);       // [1]   total: 481 ints = 1924 B < 2048

    const int tid  = threadIdx.x;
    const int cid  = blockIdx.x;
    const int wid  = tid >> 5;
    const int lane = tid & 31;
    const int g    = lane >> 2;
    const int tig  = lane & 3;

    // ============ PRE-BARRIER (all CTA-local except bfrag) ==================
    if (tid < NPOS) scnt[tid] = 0;

    // dtype probe: abs words cid*64+(tid&63) <= 127*64+63 = 8191, in-bounds
    // under BOTH int32 (16384 words) and int64 (32768 words) views.
    // int64 => odd abs words are zero high-words (values 0..15).
    const int* pos32 = (const int*)pos_raw;
    int probe_idx = cid * 64 + (tid & 63);
    int pw = pos32[probe_idx];
    int is32 = __syncthreads_or((probe_idx & 1) && (pw != 0)); // covers scnt init

    if (tid < 128) {
        int row = cid * 128 + tid;
        int p = is32 ? pos32[row] : (int)((const long long*)pos_raw)[row];
        int r = (p < 8) ? p : 8;
        parr[tid] = r;
        rnk[tid] = atomicAdd(&scnt[r], 1);
    }

    // global B fragment build: 288 entries per CTA (position-independent)
    for (int k = tid; k < BFRAG_PER_CTA; k += NTHREADS) {
        int id  = cid * BFRAG_PER_CTA + k;       // < 36864 exactly
        int p   = id >> 12;
        int rem = id & 4095;
        int qn  = rem >> 5;                      // q*16 + nb
        int ln  = rem & 31;
        int q   = qn >> 4, nb = qn & 15;
        int gg  = ln >> 2, tg = ln & 3;
        int e   = nb * 8 + gg;
        int k0  = 16 * q + 2 * tg;
        const float* Mp = table + p * D * D;
        float v0 = Mp[(k0    ) * D + e];
        float v1 = Mp[(k0 + 1) * D + e];
        float v2 = Mp[(k0 + 8) * D + e];
        float v3 = Mp[(k0 + 9) * D + e];
        uint32_t h0, l0, h1, l1;
        split2(v0, v1, h0, l0);
        split2(v2, v3, h1, l1);
        g_bfrag[id] = make_uint4(h0, h1, l0, l1);
    }
    __syncthreads();

    // prefix + worklist (thread 0, tiny)
    if (tid == 0) {
        int pre = 0;
        #pragma unroll
        for (int p = 0; p < NPOS; p++) { seg[p] = pre; pre += scnt[p]; }
        seg[NPOS] = 128;
        int n = 0;
        #pragma unroll
        for (int p = 0; p < NPOS; p++) {
            int s = seg[p], e = seg[p + 1];
            if (e > s)
                for (int b = (s >> 4); b <= ((e - 1) >> 4); b++)
                    items[n++] = make_int4(b, p, s, e);
        }
        *nitems = n;                                  // n <= 16
    }
    __syncthreads();
    if (tid < 128) perm[seg[parr[tid]] + rnk[tid]] = tid;
    __syncthreads();

    // A fragments in SORTED row order: slot(aw,q,lane,reg) byte
    // (aw*8+q)*512 + lane*16 + reg*4 ; 2 threads per row, 4 q each
    {
        int rA = tid >> 1;                    // sorted slot 0..127
        int kh = tid & 1;
        int grow = cid * 128 + perm[rA];
        int aw = rA >> 4, rr = rA & 15, gg = rr & 7, up = rr >> 3;
        #pragma unroll
        for (int qq = 0; qq < 4; qq++) {
            int q = kh * 4 + qq;
            const float4* src = (const float4*)(x + grow * D + q * 16);
            float4 f0 = src[0], f1 = src[1], f2 = src[2], f3 = src[3];
            float kv[16] = {f0.x, f0.y, f0.z, f0.w, f1.x, f1.y, f1.z, f1.w,
                            f2.x, f2.y, f2.z, f2.w, f3.x, f3.y, f3.z, f3.w};
            #pragma unroll
            for (int t = 0; t < 4; t++) {
                uint32_t hL, lL, hH, lH;
                split2(kv[2 * t], kv[2 * t + 1], hL, lL);
                split2(kv[2 * t + 8], kv[2 * t + 9], hH, lH);
                uint32_t off = (aw * 8 + q) * 512 + (gg * 4 + t) * 16 + up * 4;
                *(uint32_t*)(base + OFF_AHI + off)     = hL;
                *(uint32_t*)(base + OFF_AHI + off + 8) = hH;
                *(uint32_t*)(base + OFF_ALO + off)     = lL;
                *(uint32_t*)(base + OFF_ALO + off + 8) = lH;
            }
        }
    }

    // ============ device-wide barrier (gates bfrag only) =====================
    __syncthreads();
    if (tid == 0) {
        __threadfence();
        atomicAdd(&g_arrive, 1);
        while (*(volatile int*)&g_arrive < GRID_CTAS) { __nanosleep(32); }
        __threadfence();
    }
    __syncthreads();

    // ============ mainloop: warp-tasks = (item, colhalf) =====================
    const int n2 = 2 * (*nitems);
    for (int t = wid; t < n2; t += 8) {
        int4 it = items[t >> 1];
        int ch = t & 1;
        int b = it.x, p = it.y, s = it.z, e = it.w;

        float acc[8][4];
        #pragma unroll
        for (int nb = 0; nb < 8; nb++)
            #pragma unroll
            for (int r = 0; r < 4; r++) acc[nb][r] = 0.f;

        const uint4* bfr = g_bfrag + p * 4096;

        #pragma unroll
        for (int q = 0; q < 8; q++) {
            uint32_t abase = (b * 8 + q) * 512 + lane * 16;
            uint4 AH = *(const uint4*)(base + OFF_AHI + abase);
            uint4 AL = *(const uint4*)(base + OFF_ALO + abase);
            #pragma unroll
            for (int nb = 0; nb < 8; nb++) {
                uint4 bv = __ldg(&bfr[(q * 16 + ch * 8 + nb) * 32 + lane]);
                MMA16816(acc[nb][0], acc[nb][1], acc[nb][2], acc[nb][3],
                         AH.x, AH.y, AH.z, AH.w, bv.x, bv.y);
                MMA16816(acc[nb][0], acc[nb][1], acc[nb][2], acc[nb][3],
                         AH.x, AH.y, AH.z, AH.w, bv.z, bv.w);
                MMA16816(acc[nb][0], acc[nb][1], acc[nb][2], acc[nb][3],
                         AL.x, AL.y, AL.z, AL.w, bv.x, bv.y);
            }
        }

        // store only rows inside this item's segment
        int r0 = 16 * b + g;
        int r1 = r0 + 8;
        int grow0 = (r0 >= s && r0 < e) ? cid * 128 + perm[r0] : -1;
        int grow1 = (r1 >= s && r1 < e) ? cid * 128 + perm[r1] : -1;
        #pragma unroll
        for (int nb = 0; nb < 8; nb++) {
            int col = (ch * 8 + nb) * 8 + 2 * tig;
            if (grow0 >= 0)
                *(float2*)(out + grow0 * D + col) = make_float2(acc[nb][0], acc[nb][1]);
            if (grow1 >= 0)
                *(float2*)(out + grow1 * D + col) = make_float2(acc[nb][2], acc[nb][3]);
        }
    }

    // ============ exit: last CTA resets globals for next replay ==============
    __syncthreads();
    if (tid == 0) {
        int e = atomicAdd(&g_exit, 1);
        if (e == GRID_CTAS - 1) {
            g_arrive = 0;
            g_exit = 0;
            __threadfence();
        }
    }
}

// ---------------------------------------------------------------------------
extern "C" void kernel_launch(void* const* d_in, const int* in_sizes, int n_in,
                              void* d_out, int out_size) {
    const void*  positions = d_in[0];                 // int32/int64 [T,B] auto-detected
    const float* outputs   = (const float*)d_in[1];   // f32 [T,B,128]
    const float* table     = (const float*)d_in[2];   // f32 [9,128,128]
    float*       out       = (float*)d_out;           // f32 [T,B,128]
    (void)in_sizes; (void)n_in; (void)out_size;

    static cudaError_t attr_once = cudaFuncSetAttribute(
        fused_transfer, cudaFuncAttributeMaxDynamicSharedMemorySize, SMEM_BYTES);
    (void)attr_once;

    fused_transfer<<<GRID_CTAS, NTHREADS, SMEM_BYTES>>>(positions, outputs, table, out);
}